// round 10
// baseline (speedup 1.0000x reference)
#include <cuda_runtime.h>

#define N_NODES 20000
#define N_EDGES 320000
#define N_GRAPH 32
#define HD 64
#define H 4
#define C 64
#define L 3
#define HC (H*C)   // 256
#define LH (L*H)   // 12
#define MAXD 256   // smem-staged neighbor cap in k_layer (global fallback beyond)

// ---------------- scratch (static device globals; allocation-free) ----------------
static __device__ float d_h[N_NODES*HD];
static __device__ float d_xp[(size_t)N_NODES*HC];
static __device__ float d_as[N_NODES*H];
static __device__ float d_ad[N_NODES*H];
static __device__ float d_pool[N_GRAPH*HD];
static __device__ float d_gcnt[N_GRAPH];
static __device__ float d_wevec[L*H*HD];             // We[:,hC:(h+1)C] @ a_e[h]

// CSR by destination
static __device__ int   d_ecnt[N_NODES];
static __device__ int   d_rstart[N_NODES];
static __device__ int   d_cursor[N_NODES];
static __device__ int   d_total;
static __device__ int   d_csrc[N_EDGES];             // src at csr position
static __device__ int   d_ceid[N_EDGES];             // original edge id at csr position
static __device__ float d_aedc[(size_t)L*N_EDGES*H]; // a_ed in csr order [(l*E+pos)*4+h]
static __device__ float d_aeds[L*N_NODES*H];         // self-loop a_ed [(l*N+n)*4+h]

// ---------------- kernels ----------------
__global__ void k_init() {
    int tid = blockIdx.x*blockDim.x + threadIdx.x;
    if (tid < N_NODES)    d_ecnt[tid] = 0;
    if (tid < N_GRAPH*HD) d_pool[tid] = 0.f;
    if (tid < N_GRAPH)    d_gcnt[tid] = 0.f;
    if (tid == 0)         d_total = 0;
}

__global__ void k_node_embed(const float* __restrict__ x,
                             const float* __restrict__ W,
                             const float* __restrict__ b) {
    int tid = blockIdx.x*blockDim.x + threadIdx.x;
    if (tid >= N_NODES*HD) return;
    int n = tid >> 6, j = tid & 63;
    float a = b[j];
    #pragma unroll
    for (int k = 0; k < 3; k++) a += x[n*3+k]*W[k*HD+j];
    d_h[tid] = fmaxf(a, 0.f);
}

// wevec[l,h,k] = sum_c lin_eW[l][k, h*C+c] * att_e[l][h,c]
__global__ void k_wevec(const float* __restrict__ lin_eW,
                        const float* __restrict__ att_e) {
    __shared__ float swe[HD*(HC+1)];
    __shared__ float sae[HC];
    int l = blockIdx.x, t = threadIdx.x;
    const float* We = lin_eW + (size_t)l*HD*HC;
    for (int i = t; i < HD*HC; i += 256) {
        int k = i >> 8, r = i & 255;
        swe[k*(HC+1) + r] = We[i];
    }
    if (t < HC) sae[t] = att_e[l*HC + t];
    __syncthreads();
    int h = t >> 6, k = t & 63;
    float a = 0.f;
    #pragma unroll 8
    for (int c = 0; c < C; c++) a += swe[k*(HC+1) + h*C + c]*sae[h*C + c];
    d_wevec[l*H*HD + h*HD + k] = a;
}

// ---- CSR build ----
__global__ void k_count(const int* __restrict__ ei) {
    int tid = blockIdx.x*blockDim.x + threadIdx.x;
    if (tid >= N_EDGES) return;
    atomicAdd(&d_ecnt[ei[N_EDGES + tid]], 1);
}
__global__ void k_ranges() {
    int tid = blockIdx.x*blockDim.x + threadIdx.x;
    if (tid >= N_NODES) return;
    int c = d_ecnt[tid];
    int s = atomicAdd(&d_total, c);
    d_rstart[tid] = s;
    d_cursor[tid] = s;
}
__global__ void k_scatter(const int* __restrict__ ei) {
    int tid = blockIdx.x*blockDim.x + threadIdx.x;
    if (tid >= N_EDGES) return;
    int dst = ei[N_EDGES + tid];
    int pos = atomicAdd(&d_cursor[dst], 1);
    d_csrc[pos] = ei[tid];
    d_ceid[pos] = tid;
}

// Fused: edge embedding (registers only) -> a_ed for all L layers, in CSR order.
__global__ void __launch_bounds__(256) k_aed(const float* __restrict__ eattr,
                                             const float* __restrict__ W,
                                             const float* __restrict__ b) {
    __shared__ float sW[4*HD];
    __shared__ float sb[HD];
    __shared__ float swv[LH*HD];
    int t = threadIdx.x;
    if (t < 4*HD) sW[t] = W[t];
    if (t < HD)   sb[t] = b[t];
    for (int i = t; i < LH*HD; i += 256) swv[i] = d_wevec[i];
    __syncthreads();

    int g = blockIdx.x*blockDim.x + t;
    if (g >= N_EDGES) return;
    int e = d_ceid[g];
    float4 ua = ((const float4*)eattr)[e];

    float ea[HD];
    #pragma unroll
    for (int c = 0; c < HD; c++) {
        float v = sb[c];
        v = fmaf(ua.x, sW[0*HD+c], v);
        v = fmaf(ua.y, sW[1*HD+c], v);
        v = fmaf(ua.z, sW[2*HD+c], v);
        v = fmaf(ua.w, sW[3*HD+c], v);
        ea[c] = fmaxf(v, 0.f);
    }
    float acc[LH];
    #pragma unroll
    for (int lh = 0; lh < LH; lh++) {
        const float4* wv4 = (const float4*)&swv[lh*HD];
        float s = 0.f;
        #pragma unroll
        for (int c4 = 0; c4 < 16; c4++) {
            float4 w = wv4[c4];
            s = fmaf(ea[c4*4+0], w.x, s);
            s = fmaf(ea[c4*4+1], w.y, s);
            s = fmaf(ea[c4*4+2], w.z, s);
            s = fmaf(ea[c4*4+3], w.w, s);
        }
        acc[lh] = s;
    }
    #pragma unroll
    for (int l = 0; l < L; l++) {
        float4 o = make_float4(acc[l*4+0], acc[l*4+1], acc[l*4+2], acc[l*4+3]);
        ((float4*)d_aedc)[(size_t)l*N_EDGES + g] = o;
    }
}

// Self-loop a_ed = mean of incoming a_ed (linearity).
__global__ void k_aeds() {
    int tid = blockIdx.x*blockDim.x + threadIdx.x;
    if (tid >= L*N_NODES) return;
    int l = tid / N_NODES, n = tid % N_NODES;
    int start = d_rstart[n], cnt = d_ecnt[n];
    const float4* a4 = (const float4*)d_aedc + (size_t)l*N_EDGES;
    float4 s = make_float4(0.f, 0.f, 0.f, 0.f);
    for (int i = 0; i < cnt; i++) {
        float4 v = a4[start + i];
        s.x += v.x; s.y += v.y; s.z += v.z; s.w += v.w;
    }
    float inv = 1.f / fmaxf((float)cnt, 1.f);
    s.x *= inv; s.y *= inv; s.z *= inv; s.w *= inv;
    ((float4*)d_aeds)[l*N_NODES + n] = s;
}

// xp = h @ W + a_src/a_dst reductions. 8 nodes per block.
__global__ void __launch_bounds__(256) k_xp(const float* __restrict__ linW,
                                            const float* __restrict__ asrc,
                                            const float* __restrict__ adst) {
    int n0 = blockIdx.x*8, j = threadIdx.x;
    __shared__ float hrow[8][HD];
    __shared__ float sms[8][8], smd[8][8];   // [warp][node]
    for (int i = j; i < 8*HD; i += 256) hrow[i >> 6][i & 63] = d_h[n0*HD + i];
    __syncthreads();

    float acc[8];
    #pragma unroll
    for (int m = 0; m < 8; m++) acc[m] = 0.f;
    #pragma unroll
    for (int k = 0; k < HD; k += 4) {
        float w0 = linW[(k+0)*HC + j];
        float w1 = linW[(k+1)*HC + j];
        float w2 = linW[(k+2)*HC + j];
        float w3 = linW[(k+3)*HC + j];
        #pragma unroll
        for (int m = 0; m < 8; m++) {
            float4 hv = *(const float4*)&hrow[m][k];
            acc[m] = fmaf(hv.x, w0, acc[m]);
            acc[m] = fmaf(hv.y, w1, acc[m]);
            acc[m] = fmaf(hv.z, w2, acc[m]);
            acc[m] = fmaf(hv.w, w3, acc[m]);
        }
    }
    #pragma unroll
    for (int m = 0; m < 8; m++)
        d_xp[(size_t)(n0+m)*HC + j] = acc[m];

    float as_ = asrc[j], ad_ = adst[j];
    float ps[8], pd[8];
    #pragma unroll
    for (int m = 0; m < 8; m++) { ps[m] = acc[m]*as_; pd[m] = acc[m]*ad_; }
    #pragma unroll
    for (int o = 16; o > 0; o >>= 1) {
        #pragma unroll
        for (int m = 0; m < 8; m++) {
            ps[m] += __shfl_down_sync(0xffffffffu, ps[m], o);
            pd[m] += __shfl_down_sync(0xffffffffu, pd[m], o);
        }
    }
    int w = j >> 5;
    if ((j & 31) == 0) {
        #pragma unroll
        for (int m = 0; m < 8; m++) { sms[w][m] = ps[m]; smd[w][m] = pd[m]; }
    }
    __syncthreads();
    if (j < 32) {
        int m = j >> 2, hh = j & 3;
        d_as[(n0+m)*H + hh] = sms[2*hh][m] + sms[2*hh+1][m];
    } else if (j < 64) {
        int tt = j - 32, m = tt >> 2, hh = tt & 3;
        d_ad[(n0+m)*H + hh] = smd[2*hh][m] + smd[2*hh+1][m];
    }
}

// Fused layer, single pass (no max-shift: exp(a)/sum(exp(a)) is identical).
// Block per dst node; thread j owns channel j (head = j>>6).
__global__ void __launch_bounds__(256) k_layer(int l, const float* __restrict__ convb) {
    int n = blockIdx.x, j = threadIdx.x;
    int h = j >> 6;
    __shared__ int   ssrc[MAXD];
    __shared__ float saed[MAXD*H];
    __shared__ float sm_acc[HC];

    int start = d_rstart[n], cnt = d_ecnt[n];
    int m = (cnt < MAXD) ? cnt : MAXD;
    const float*  aedl = d_aedc + (size_t)l*N_EDGES*H;
    const float4* aed4 = (const float4*)aedl;

    for (int i = j; i < m; i += 256) {
        ssrc[i] = d_csrc[start + i];
        ((float4*)saed)[i] = aed4[start + i];
    }

    float adn = d_ad[n*H + h];
    float a0 = d_as[n*H + h] + adn + d_aeds[(l*N_NODES + n)*H + h];
    a0 = (a0 > 0.f) ? a0 : 0.2f*a0;
    float wself = __expf(a0);
    float den = wself;
    float acc = wself * d_xp[(size_t)n*HC + j];
    __syncthreads();

    int i = 0;
    for (; i + 4 <= m; i += 4) {
        int s0 = ssrc[i+0], s1 = ssrc[i+1], s2 = ssrc[i+2], s3 = ssrc[i+3];
        float x0 = d_xp[(size_t)s0*HC + j];
        float x1 = d_xp[(size_t)s1*HC + j];
        float x2 = d_xp[(size_t)s2*HC + j];
        float x3 = d_xp[(size_t)s3*HC + j];
        float b0 = d_as[s0*H + h] + adn + saed[(i+0)*H + h];
        float b1 = d_as[s1*H + h] + adn + saed[(i+1)*H + h];
        float b2 = d_as[s2*H + h] + adn + saed[(i+2)*H + h];
        float b3 = d_as[s3*H + h] + adn + saed[(i+3)*H + h];
        b0 = (b0 > 0.f) ? b0 : 0.2f*b0;
        b1 = (b1 > 0.f) ? b1 : 0.2f*b1;
        b2 = (b2 > 0.f) ? b2 : 0.2f*b2;
        b3 = (b3 > 0.f) ? b3 : 0.2f*b3;
        float w0 = __expf(b0), w1 = __expf(b1), w2 = __expf(b2), w3 = __expf(b3);
        den += w0 + w1 + w2 + w3;
        acc = fmaf(w0, x0, acc);
        acc = fmaf(w1, x1, acc);
        acc = fmaf(w2, x2, acc);
        acc = fmaf(w3, x3, acc);
    }
    for (; i < m; i++) {
        int src = ssrc[i];
        float a = d_as[src*H + h] + adn + saed[i*H + h];
        a = (a > 0.f) ? a : 0.2f*a;
        float w = __expf(a);
        den += w;
        acc = fmaf(w, d_xp[(size_t)src*HC + j], acc);
    }
    // rare fallback: degree beyond smem cap
    for (int q = MAXD; q < cnt; q++) {
        int src = d_csrc[start + q];
        float a = d_as[src*H + h] + adn + aedl[(size_t)(start+q)*H + h];
        a = (a > 0.f) ? a : 0.2f*a;
        float w = __expf(a);
        den += w;
        acc = fmaf(w, d_xp[(size_t)src*HC + j], acc);
    }

    sm_acc[j] = acc / den;
    __syncthreads();
    if (j < HD) {
        float s = sm_acc[j] + sm_acc[j+64] + sm_acc[j+128] + sm_acc[j+192];
        d_h[n*HD + j] = fmaxf(0.25f*s + convb[j], 0.f);
    }
}

__global__ void k_pool(const int* __restrict__ batch) {
    int tid = blockIdx.x*blockDim.x + threadIdx.x;
    if (tid >= N_NODES*HD) return;
    int n = tid >> 6, c = tid & 63;
    int b = batch[n];
    atomicAdd(&d_pool[b*HD+c], d_h[tid]);
    if (c == 0) atomicAdd(&d_gcnt[b], 1.f);
}

__global__ void k_head(const float* __restrict__ u,
                       const float* __restrict__ gW, const float* __restrict__ gb,
                       const float* __restrict__ f1W, const float* __restrict__ f1b,
                       const float* __restrict__ f2W, const float* __restrict__ f2b,
                       float* __restrict__ out) {
    int b = blockIdx.x, t = threadIdx.x;
    __shared__ float z[2*HD], z2[HD];
    float cn = fmaxf(d_gcnt[b], 1.f);
    z[t] = d_pool[b*HD+t] / cn;
    float ug = gb[t];
    #pragma unroll
    for (int k = 0; k < 10; k++) ug += u[b*10+k]*gW[k*HD+t];
    z[HD+t] = fmaxf(ug, 0.f);
    __syncthreads();
    float v = f1b[t];
    #pragma unroll 8
    for (int k = 0; k < 2*HD; k++) v += z[k]*f1W[k*HD+t];
    z2[t] = fmaxf(v, 0.f);
    __syncthreads();
    if (t < 2) {
        float o = f2b[t];
        #pragma unroll 8
        for (int k = 0; k < HD; k++) o += z2[k]*f2W[k*2+t];
        out[b*2+t] = o;
    }
}

// ---------------- launch ----------------
extern "C" void kernel_launch(void* const* d_in, const int* in_sizes, int n_in,
                              void* d_out, int out_size) {
    const float* x      = (const float*)d_in[0];
    const int*   ei     = (const int*)  d_in[1];   // [2,E]
    const float* eattr  = (const float*)d_in[2];
    const float* u      = (const float*)d_in[3];
    const int*   batch  = (const int*)  d_in[4];
    const float* node_W = (const float*)d_in[5];
    const float* node_b = (const float*)d_in[6];
    const float* eemb_W = (const float*)d_in[7];
    const float* eemb_b = (const float*)d_in[8];
    const float* lin_W  = (const float*)d_in[9];
    const float* att_src= (const float*)d_in[10];
    const float* att_dst= (const float*)d_in[11];
    const float* lin_eW = (const float*)d_in[12];
    const float* att_e  = (const float*)d_in[13];
    const float* conv_b = (const float*)d_in[14];
    const float* gW     = (const float*)d_in[15];
    const float* gb     = (const float*)d_in[16];
    const float* f1W    = (const float*)d_in[17];
    const float* f1b    = (const float*)d_in[18];
    const float* f2W    = (const float*)d_in[19];
    const float* f2b    = (const float*)d_in[20];
    float* out = (float*)d_out;

    const int TB = 256;
    int gNH = (N_NODES*HD + TB-1)/TB;
    int gE  = (N_EDGES + TB-1)/TB;
    int gN  = (N_NODES + TB-1)/TB;

    k_init<<<gN, TB>>>();
    k_node_embed<<<gNH, TB>>>(x, node_W, node_b);
    k_wevec<<<L, TB>>>(lin_eW, att_e);

    // CSR build
    k_count<<<gE, TB>>>(ei);
    k_ranges<<<gN, TB>>>();
    k_scatter<<<gE, TB>>>(ei);

    // edge attention terms for all layers
    k_aed<<<gE, TB>>>(eattr, eemb_W, eemb_b);
    k_aeds<<<(L*N_NODES + TB-1)/TB, TB>>>();

    for (int l = 0; l < L; l++) {
        k_xp<<<N_NODES/8, HC>>>(lin_W + (size_t)l*HD*HC,
                                att_src + l*HC, att_dst + l*HC);
        k_layer<<<N_NODES, HC>>>(l, conv_b + l*C);
    }

    k_pool<<<gNH, TB>>>(batch);
    k_head<<<N_GRAPH, HD>>>(u, gW, gb, f1W, f1b, f2W, f2b, out);
}

// round 13
// speedup vs baseline: 1.0797x; 1.0797x over previous
#include <cuda_runtime.h>
#include <cuda_fp16.h>

#define N_NODES 20000
#define N_EDGES 320000
#define N_GRAPH 32
#define HD 64
#define H 4
#define C 64
#define L 3
#define HC (H*C)   // 256
#define LH (L*H)   // 12
#define MAXD 256   // smem-cached max in-degree in k_layer (fallback path beyond)

// ---------------- scratch (static device globals; allocation-free) ----------------
static __device__ float  d_h[N_NODES*HD];
static __device__ __half d_xph[(size_t)N_NODES*HC];   // fp16 projected features (aggregation only)
static __device__ float  d_as[N_NODES*H];
static __device__ float  d_ad[N_NODES*H];
static __device__ float  d_pool[N_GRAPH*HD];
static __device__ float  d_gcnt[N_GRAPH];
static __device__ float  d_wevec[L*H*HD];

// CSR by destination
static __device__ int   d_ecnt[N_NODES];
static __device__ int   d_rstart[N_NODES];
static __device__ int   d_cursor[N_NODES];
static __device__ int   d_total;
static __device__ int   d_csrc[N_EDGES];
static __device__ int   d_ceid[N_EDGES];
static __device__ float d_aedc[(size_t)L*N_EDGES*H];
static __device__ float d_aeds[L*N_NODES*H];

// ---------------- kernels ----------------
__global__ void k_init() {
    int tid = blockIdx.x*blockDim.x + threadIdx.x;
    if (tid < N_NODES)    d_ecnt[tid] = 0;
    if (tid < N_GRAPH*HD) d_pool[tid] = 0.f;
    if (tid < N_GRAPH)    d_gcnt[tid] = 0.f;
    if (tid == 0)         d_total = 0;
}

__global__ void k_node_embed(const float* __restrict__ x,
                             const float* __restrict__ W,
                             const float* __restrict__ b) {
    int tid = blockIdx.x*blockDim.x + threadIdx.x;
    if (tid >= N_NODES*HD) return;
    int n = tid >> 6, j = tid & 63;
    float a = b[j];
    #pragma unroll
    for (int k = 0; k < 3; k++) a += x[n*3+k]*W[k*HD+j];
    d_h[tid] = fmaxf(a, 0.f);
}

// wevec[l,h,k] = sum_c lin_eW[l][k, h*C+c] * att_e[l][h,c]
__global__ void k_wevec(const float* __restrict__ lin_eW,
                        const float* __restrict__ att_e) {
    __shared__ float swe[HD*(HC+1)];
    __shared__ float sae[HC];
    int l = blockIdx.x, t = threadIdx.x;
    const float* We = lin_eW + (size_t)l*HD*HC;
    for (int i = t; i < HD*HC; i += 256) {
        int k = i >> 8, r = i & 255;
        swe[k*(HC+1) + r] = We[i];
    }
    if (t < HC) sae[t] = att_e[l*HC + t];
    __syncthreads();
    int h = t >> 6, k = t & 63;
    float a = 0.f;
    #pragma unroll 8
    for (int c = 0; c < C; c++) a += swe[k*(HC+1) + h*C + c]*sae[h*C + c];
    d_wevec[l*H*HD + h*HD + k] = a;
}

// ---- CSR build ----
__global__ void k_count(const int* __restrict__ ei) {
    int tid = blockIdx.x*blockDim.x + threadIdx.x;
    if (tid >= N_EDGES) return;
    atomicAdd(&d_ecnt[ei[N_EDGES + tid]], 1);
}
__global__ void k_ranges() {
    int tid = blockIdx.x*blockDim.x + threadIdx.x;
    if (tid >= N_NODES) return;
    int c = d_ecnt[tid];
    int s = atomicAdd(&d_total, c);
    d_rstart[tid] = s;
    d_cursor[tid] = s;
}
__global__ void k_scatter(const int* __restrict__ ei) {
    int tid = blockIdx.x*blockDim.x + threadIdx.x;
    if (tid >= N_EDGES) return;
    int dst = ei[N_EDGES + tid];
    int pos = atomicAdd(&d_cursor[dst], 1);
    d_csrc[pos] = ei[tid];
    d_ceid[pos] = tid;
}

// Fused: edge embedding (registers only) -> a_ed for all L layers, in CSR order.
__global__ void __launch_bounds__(256) k_aed(const float* __restrict__ eattr,
                                             const float* __restrict__ W,
                                             const float* __restrict__ b) {
    __shared__ float sW[4*HD];
    __shared__ float sb[HD];
    __shared__ float swv[LH*HD];
    int t = threadIdx.x;
    if (t < 4*HD) sW[t] = W[t];
    if (t < HD)   sb[t] = b[t];
    for (int i = t; i < LH*HD; i += 256) swv[i] = d_wevec[i];
    __syncthreads();

    int g = blockIdx.x*blockDim.x + t;
    if (g >= N_EDGES) return;
    int e = d_ceid[g];
    float4 ua = ((const float4*)eattr)[e];

    float ea[HD];
    #pragma unroll
    for (int c = 0; c < HD; c++) {
        float v = sb[c];
        v = fmaf(ua.x, sW[0*HD+c], v);
        v = fmaf(ua.y, sW[1*HD+c], v);
        v = fmaf(ua.z, sW[2*HD+c], v);
        v = fmaf(ua.w, sW[3*HD+c], v);
        ea[c] = fmaxf(v, 0.f);
    }
    float acc[LH];
    #pragma unroll
    for (int lh = 0; lh < LH; lh++) {
        const float4* wv4 = (const float4*)&swv[lh*HD];
        float s = 0.f;
        #pragma unroll
        for (int c4 = 0; c4 < 16; c4++) {
            float4 w = wv4[c4];
            s = fmaf(ea[c4*4+0], w.x, s);
            s = fmaf(ea[c4*4+1], w.y, s);
            s = fmaf(ea[c4*4+2], w.z, s);
            s = fmaf(ea[c4*4+3], w.w, s);
        }
        acc[lh] = s;
    }
    #pragma unroll
    for (int l = 0; l < L; l++) {
        float4 o = make_float4(acc[l*4+0], acc[l*4+1], acc[l*4+2], acc[l*4+3]);
        ((float4*)d_aedc)[(size_t)l*N_EDGES + g] = o;
    }
}

// Self-loop a_ed = mean of incoming a_ed (linearity).
__global__ void k_aeds() {
    int tid = blockIdx.x*blockDim.x + threadIdx.x;
    if (tid >= L*N_NODES) return;
    int l = tid / N_NODES, n = tid % N_NODES;
    int start = d_rstart[n], cnt = d_ecnt[n];
    const float4* a4 = (const float4*)d_aedc + (size_t)l*N_EDGES;
    float4 s = make_float4(0.f, 0.f, 0.f, 0.f);
    for (int i = 0; i < cnt; i++) {
        float4 v = a4[start + i];
        s.x += v.x; s.y += v.y; s.z += v.z; s.w += v.w;
    }
    float inv = 1.f / fmaxf((float)cnt, 1.f);
    s.x *= inv; s.y *= inv; s.z *= inv; s.w *= inv;
    ((float4*)d_aeds)[l*N_NODES + n] = s;
}

// per-layer: xp = h @ W + a_src/a_dst reductions. 4 nodes per block.
__global__ void k_xp(const float* __restrict__ linW,
                     const float* __restrict__ asrc,
                     const float* __restrict__ adst) {
    int n0 = blockIdx.x*4, j = threadIdx.x;
    __shared__ float hrow[4][HD];
    __shared__ float sms[8][4], smd[8][4];
    hrow[j >> 6][j & 63] = d_h[n0*HD + j];
    __syncthreads();
    float a0 = 0.f, a1 = 0.f, a2 = 0.f, a3 = 0.f;
    #pragma unroll 16
    for (int k = 0; k < HD; k++) {
        float w = linW[k*HC + j];
        a0 = fmaf(hrow[0][k], w, a0);
        a1 = fmaf(hrow[1][k], w, a1);
        a2 = fmaf(hrow[2][k], w, a2);
        a3 = fmaf(hrow[3][k], w, a3);
    }
    d_xph[(size_t)(n0+0)*HC + j] = __float2half(a0);
    d_xph[(size_t)(n0+1)*HC + j] = __float2half(a1);
    d_xph[(size_t)(n0+2)*HC + j] = __float2half(a2);
    d_xph[(size_t)(n0+3)*HC + j] = __float2half(a3);
    float as_ = asrc[j], ad_ = adst[j];
    float ps[4] = {a0*as_, a1*as_, a2*as_, a3*as_};
    float pd[4] = {a0*ad_, a1*ad_, a2*ad_, a3*ad_};
    #pragma unroll
    for (int o = 16; o > 0; o >>= 1) {
        #pragma unroll
        for (int m = 0; m < 4; m++) {
            ps[m] += __shfl_down_sync(0xffffffffu, ps[m], o);
            pd[m] += __shfl_down_sync(0xffffffffu, pd[m], o);
        }
    }
    int w = j >> 5;
    if ((j & 31) == 0) {
        #pragma unroll
        for (int m = 0; m < 4; m++) { sms[w][m] = ps[m]; smd[w][m] = pd[m]; }
    }
    __syncthreads();
    if (j < 16) {
        int m = j >> 2, hh = j & 3;
        d_as[(n0+m)*H + hh] = sms[2*hh][m] + sms[2*hh+1][m];
    } else if (j < 32) {
        int tt = j - 16, m = tt >> 2, hh = tt & 3;
        d_ad[(n0+m)*H + hh] = smd[2*hh][m] + smd[2*hh+1][m];
    }
}

// Fused layer: alpha + segment softmax + aggregation + head-mean + bias + relu.
// Two-pass with smem-cached alpha/src (round-4 structure). fp16 xp gathers.
__global__ void __launch_bounds__(256) k_layer(int l, const float* __restrict__ convb) {
    int n = blockIdx.x, j = threadIdx.x;
    int h = j >> 6, i0 = j & 63;
    __shared__ float sm_alpha[H*MAXD];
    __shared__ int   sm_src[MAXD];
    __shared__ float sm_wmax[8];
    __shared__ float sm_m[H], sm_aself[H];
    __shared__ float sm_acc[HC];

    int start = d_rstart[n], cnt = d_ecnt[n];
    bool fits = (cnt <= MAXD);
    float adn = d_ad[n*H + h];
    const float* aedl = d_aedc + (size_t)l*N_EDGES*H;

    if (j < H) {
        float a = d_as[n*H+j] + d_ad[n*H+j] + d_aeds[(l*N_NODES + n)*H + j];
        sm_aself[j] = (a > 0.f) ? a : 0.2f*a;
    }

    // Pass A: compute alphas (cache in smem), per-thread max
    float lmax = -1e30f;
    for (int i = i0; i < cnt; i += 64) {
        int src = d_csrc[start + i];
        float a = d_as[src*H + h] + adn + aedl[(size_t)(start+i)*H + h];
        a = (a > 0.f) ? a : 0.2f*a;
        if (fits) {
            sm_alpha[h*MAXD + i] = a;
            if (h == 0) sm_src[i] = src;
        }
        lmax = fmaxf(lmax, a);
    }
    #pragma unroll
    for (int o = 16; o > 0; o >>= 1)
        lmax = fmaxf(lmax, __shfl_xor_sync(0xffffffffu, lmax, o));
    if ((j & 31) == 0) sm_wmax[j >> 5] = lmax;
    __syncthreads();
    if (j < H) sm_m[j] = fmaxf(sm_aself[j], fmaxf(sm_wmax[2*j], sm_wmax[2*j+1]));
    __syncthreads();

    // Pass B: weighted gather (fp16 feature rows, fp32 accumulate)
    float mh = sm_m[h];
    float wself = __expf(sm_aself[h] - mh);
    float den = wself;
    float acc = wself * __half2float(d_xph[(size_t)n*HC + j]);
    if (fits) {
        for (int i = 0; i < cnt; i++) {
            float w = __expf(sm_alpha[h*MAXD + i] - mh);
            int src = sm_src[i];
            acc = fmaf(w, __half2float(d_xph[(size_t)src*HC + j]), acc);
            den += w;
        }
    } else {
        for (int i = 0; i < cnt; i++) {
            int src = d_csrc[start + i];
            float a = d_as[src*H + h] + adn + aedl[(size_t)(start+i)*H + h];
            a = (a > 0.f) ? a : 0.2f*a;
            float w = __expf(a - mh);
            acc = fmaf(w, __half2float(d_xph[(size_t)src*HC + j]), acc);
            den += w;
        }
    }
    sm_acc[j] = acc / den;
    __syncthreads();
    if (j < HD) {
        float s = sm_acc[j] + sm_acc[j+64] + sm_acc[j+128] + sm_acc[j+192];
        d_h[n*HD + j] = fmaxf(0.25f*s + convb[j], 0.f);
    }
}

__global__ void k_pool(const int* __restrict__ batch) {
    int tid = blockIdx.x*blockDim.x + threadIdx.x;
    if (tid >= N_NODES*HD) return;
    int n = tid >> 6, c = tid & 63;
    int b = batch[n];
    atomicAdd(&d_pool[b*HD+c], d_h[tid]);
    if (c == 0) atomicAdd(&d_gcnt[b], 1.f);
}

__global__ void k_head(const float* __restrict__ u,
                       const float* __restrict__ gW, const float* __restrict__ gb,
                       const float* __restrict__ f1W, const float* __restrict__ f1b,
                       const float* __restrict__ f2W, const float* __restrict__ f2b,
                       float* __restrict__ out) {
    int b = blockIdx.x, t = threadIdx.x;
    __shared__ float z[2*HD], z2[HD];
    float cn = fmaxf(d_gcnt[b], 1.f);
    z[t] = d_pool[b*HD+t] / cn;
    float ug = gb[t];
    #pragma unroll
    for (int k = 0; k < 10; k++) ug += u[b*10+k]*gW[k*HD+t];
    z[HD+t] = fmaxf(ug, 0.f);
    __syncthreads();
    float v = f1b[t];
    #pragma unroll 8
    for (int k = 0; k < 2*HD; k++) v += z[k]*f1W[k*HD+t];
    z2[t] = fmaxf(v, 0.f);
    __syncthreads();
    if (t < 2) {
        float o = f2b[t];
        #pragma unroll 8
        for (int k = 0; k < HD; k++) o += z2[k]*f2W[k*2+t];
        out[b*2+t] = o;
    }
}

// ---------------- launch ----------------
extern "C" void kernel_launch(void* const* d_in, const int* in_sizes, int n_in,
                              void* d_out, int out_size) {
    const float* x      = (const float*)d_in[0];
    const int*   ei     = (const int*)  d_in[1];   // [2,E]
    const float* eattr  = (const float*)d_in[2];
    const float* u      = (const float*)d_in[3];
    const int*   batch  = (const int*)  d_in[4];
    const float* node_W = (const float*)d_in[5];
    const float* node_b = (const float*)d_in[6];
    const float* eemb_W = (const float*)d_in[7];
    const float* eemb_b = (const float*)d_in[8];
    const float* lin_W  = (const float*)d_in[9];
    const float* att_src= (const float*)d_in[10];
    const float* att_dst= (const float*)d_in[11];
    const float* lin_eW = (const float*)d_in[12];
    const float* att_e  = (const float*)d_in[13];
    const float* conv_b = (const float*)d_in[14];
    const float* gW     = (const float*)d_in[15];
    const float* gb     = (const float*)d_in[16];
    const float* f1W    = (const float*)d_in[17];
    const float* f1b    = (const float*)d_in[18];
    const float* f2W    = (const float*)d_in[19];
    const float* f2b    = (const float*)d_in[20];
    float* out = (float*)d_out;

    const int TB = 256;
    int gNH = (N_NODES*HD + TB-1)/TB;
    int gE  = (N_EDGES + TB-1)/TB;
    int gN  = (N_NODES + TB-1)/TB;

    k_init<<<gN, TB>>>();
    k_node_embed<<<gNH, TB>>>(x, node_W, node_b);
    k_wevec<<<L, TB>>>(lin_eW, att_e);

    // CSR build
    k_count<<<gE, TB>>>(ei);
    k_ranges<<<gN, TB>>>();
    k_scatter<<<gE, TB>>>(ei);

    // edge attention terms for all layers
    k_aed<<<gE, TB>>>(eattr, eemb_W, eemb_b);
    k_aeds<<<(L*N_NODES + TB-1)/TB, TB>>>();

    for (int l = 0; l < L; l++) {
        k_xp<<<N_NODES/4, HC>>>(lin_W + (size_t)l*HD*HC,
                                att_src + l*HC, att_dst + l*HC);
        k_layer<<<N_NODES, HC>>>(l, conv_b + l*C);
    }

    k_pool<<<gNH, TB>>>(batch);
    k_head<<<N_GRAPH, HD>>>(u, gW, gb, f1W, f1b, f2W, f2b, out);
}